// round 13
// baseline (speedup 1.0000x reference)
#include <cuda_runtime.h>
#include <cstdint>

// ---------------- problem constants ----------------
#define Bn    32
#define Hn    384
#define Wn    384
#define ITERS 5
#define NPIX  (Bn * Hn * Wn)
#define NELEM (NPIX * 8)

// ---------------- tile config ----------------
#define TY 16                 // output rows per CTA
#define TX 32                 // output pixels per CTA
#define QR 22                 // q tile rows  (TY + 6 halo)
#define QP 40                 // q tile pixels (TX + 6 halo, padded to 40)

// ---------------- device scratch ----------------
// q marginals stored as bf16x2 words: 4 words per pixel (8 channels)
__device__ uint32_t g_qb[2][NPIX * 4];
__device__ float    g_uw[NELEM];     // u @ W2 (fp32)

__device__ __forceinline__ uint32_t pack_bf16(float lo, float hi) {
    uint32_t r;
    asm("cvt.rn.bf16x2.f32 %0, %1, %2;" : "=r"(r) : "f"(hi), "f"(lo));
    return r;
}

// m16n8k16 bf16 MMA: D(16x8,f32) += A(16x16,row) * B(16x8,col)
__device__ __forceinline__ void mma_bf16(float* c,
                                         uint32_t a0, uint32_t a1,
                                         uint32_t a2, uint32_t a3,
                                         uint32_t b0, uint32_t b1) {
    asm volatile(
        "mma.sync.aligned.m16n8k16.row.col.f32.bf16.bf16.f32 "
        "{%0,%1,%2,%3}, {%4,%5,%6,%7}, {%8,%9}, {%0,%1,%2,%3};"
        : "+f"(c[0]), "+f"(c[1]), "+f"(c[2]), "+f"(c[3])
        : "r"(a0), "r"(a1), "r"(a2), "r"(a3), "r"(b0), "r"(b1));
}

// ldmatrix x4: loads the full 16x16 bf16 A fragment in one instruction
__device__ __forceinline__ void ldmatrix_x4(uint32_t& r0, uint32_t& r1,
                                            uint32_t& r2, uint32_t& r3,
                                            uint32_t addr) {
    asm volatile("ldmatrix.sync.aligned.m8n8.x4.shared.b16 {%0,%1,%2,%3}, [%4];"
                 : "=r"(r0), "=r"(r1), "=r"(r2), "=r"(r3) : "r"(addr));
}

// ---------------------------------------------------------------------------
// Prologue: q0 = softmax(x) (stored bf16x2); uw = (-log(clip(q0))) @ W2 (fp32)
// ---------------------------------------------------------------------------
__global__ void __launch_bounds__(256) mrf_prologue(const float* __restrict__ x,
                                                    const float* __restrict__ ksw) {
    __shared__ float sW[64];
    if (threadIdx.x < 64) sW[threadIdx.x] = ksw[threadIdx.x];
    __syncthreads();

    int p = blockIdx.x * 256 + threadIdx.x;
    if (p >= NPIX) return;
    const float4* xp = (const float4*)(x + (size_t)p * 8);
    float4 a = xp[0], b = xp[1];
    float v[8] = {a.x, a.y, a.z, a.w, b.x, b.y, b.z, b.w};

    float m = v[0];
#pragma unroll
    for (int i = 1; i < 8; i++) m = fmaxf(m, v[i]);
    float e[8], s = 0.f;
#pragma unroll
    for (int i = 0; i < 8; i++) { e[i] = __expf(v[i] - m); s += e[i]; }
    float inv = __fdividef(1.f, s);

    float q[8], u[8];
#pragma unroll
    for (int i = 0; i < 8; i++) {
        q[i] = e[i] * inv;
        u[i] = -__logf(fmaxf(q[i], 1e-6f));
    }
    float uw[8];
#pragma unroll
    for (int d = 0; d < 8; d++) {
        float acc = 0.f;
#pragma unroll
        for (int c = 0; c < 8; c++) acc += u[c] * sW[c * 8 + d];
        uw[d] = acc;
    }
    uint4 qw;
    qw.x = pack_bf16(q[0], q[1]);
    qw.y = pack_bf16(q[2], q[3]);
    qw.z = pack_bf16(q[4], q[5]);
    qw.w = pack_bf16(q[6], q[7]);
    ((uint4*)(&g_qb[0][(size_t)p * 4]))[0] = qw;
    float4* up = (float4*)(&g_uw[(size_t)p * 8]);
    up[0] = make_float4(uw[0], uw[1], uw[2], uw[3]);
    up[1] = make_float4(uw[4], uw[5], uw[6], uw[7]);
}

// ---------------------------------------------------------------------------
// One iteration via bf16 m16n8k16 mma.sync + ldmatrix, dx tap-pairs in K.
// CTA = 16 rows x 32 px, 8 warps; warp w owns rows {2w,2w+1} x two halves.
// ---------------------------------------------------------------------------
__global__ void __launch_bounds__(256, 3) mrf_iter_mma(
    const float* __restrict__ kint,
    const float* __restrict__ ksw,
    const float* __restrict__ ksb,
    float* __restrict__ out,
    int parity, int last)
{
    // q tile: bf16x2 words, 4 per pixel (row-major, QP pixels per row)
    __shared__ __align__(16) uint32_t sq[QR * QP * 4];
    // fused tap-pair weights, b0/b1 adjacent for LDS.64:
    // sBp[pair*64 + (tq*8+g)*2 + h], h=0: tap dx0 word, h=1: tap dx0+1 word
    __shared__ __align__(16) uint32_t sBp[28 * 64];

    const int t    = threadIdx.x;
    const int w    = t >> 5;
    const int lane = t & 31;
    const int g    = lane >> 2;    // groupID 0..7
    const int tq   = lane & 3;     // threadID_in_group 0..3

    const int b  = blockIdx.z;
    const int y0 = blockIdx.y * TY;
    const int x0 = blockIdx.x * TX;
    const uint32_t* __restrict__ qin  = g_qb[parity];
    uint32_t* __restrict__       qout = g_qb[parity ^ 1];

    // --- build fused pair weights.
    // index i: pair=i>>6, rem=i&63; h=rem&1; idx=rem>>1; tqi=idx>>3; n=idx&7
    // dx = 2*(pair&3)+h, dy = pair>>2; zero word if dx>6.
    // word = {lo: Bf[tap][2tqi][n], hi: Bf[tap][2tqi+1][n]},
    // Bf[tap][k][n] = sum_{c!=k} K[tap][k][c] * W2[c][n]
    for (int i = t; i < 28 * 64; i += 256) {
        int pair = i >> 6, rem = i & 63;
        int h = rem & 1, idx = rem >> 1, tqi = idx >> 3, n = idx & 7;
        int dy = pair >> 2, dx = 2 * (pair & 3) + h;
        uint32_t word = 0;
        if (dx < 7) {
            int tap = dy * 7 + dx;
            float v0 = 0.f, v1 = 0.f;
            const float* kp0 = kint + tap * 64 + (2 * tqi) * 8;
#pragma unroll
            for (int c = 0; c < 8; c++) {
                float wcn = __ldg(ksw + c * 8 + n);
                if (c != 2 * tqi)     v0 += __ldg(kp0 + c) * wcn;
                if (c != 2 * tqi + 1) v1 += __ldg(kp0 + 8 + c) * wcn;
            }
            word = pack_bf16(v0, v1);
        }
        sBp[i] = word;
    }

    // --- stage q tile (rows y0-3..y0+18, px x0-3..x0+36), bf16x2 words
    for (int i = t; i < QR * QP; i += 256) {
        int qr = i / QP, px = i - qr * QP;
        int gy = y0 + qr - 3, gx = x0 + px - 3;
        uint4 qw = make_uint4(0u, 0u, 0u, 0u);
        if (gy >= 0 && gy < Hn && gx >= 0 && gx < Wn)
            qw = ((const uint4*)(qin + ((((size_t)b * Hn + gy) * Wn) + gx) * 4))[0];
        ((uint4*)sq)[i] = qw;
    }
    __syncthreads();

    // --- mainloop: 7 dy x 4 dx-pairs x 4 strips
    float acc[4][4];
#pragma unroll
    for (int s = 0; s < 4; s++)
#pragma unroll
        for (int j = 0; j < 4; j++) acc[s][j] = 0.f;

    const int rw0 = 2 * w;
    // ldmatrix lane -> pixel offset: tiles [m-lo/k-lo, m-hi/k-lo, m-lo/k-hi,
    // m-hi/k-hi]; k-hi = next pixel (tap dx0+1)
    const int laneoff = (lane & 7) + ((lane & 8) ? 8 : 0) + ((lane & 16) ? 1 : 0);
    const uint32_t sq_base = (uint32_t)__cvta_generic_to_shared(sq);

#pragma unroll 1
    for (int dy = 0; dy < 7; dy++) {
        uint32_t abase[4];
#pragma unroll
        for (int s = 0; s < 4; s++)
            abase[s] = sq_base +
                (((rw0 + dy + (s >> 1)) * QP + (s & 1) * 16 + laneoff) << 4);
#pragma unroll
        for (int pi = 0; pi < 4; pi++) {
            uint2 bw = *(const uint2*)(sBp + ((dy * 4 + pi) << 6)
                                           + ((tq * 8 + g) << 1));
#pragma unroll
            for (int s = 0; s < 4; s++) {
                uint32_t a0, a1, a2, a3;
                ldmatrix_x4(a0, a1, a2, a3, abase[s] + (pi << 5));
                mma_bf16(acc[s], a0, a1, a2, a3, bw.x, bw.y);
            }
        }
    }

    // --- epilogue: lane owns pixels (g, g+8) x channels (2tq, 2tq+1) per strip
    const float bx = __ldg(ksb + 2 * tq);
    const float by = __ldg(ksb + 2 * tq + 1);

#pragma unroll
    for (int s = 0; s < 4; s++) {
        const int gy = y0 + rw0 + (s >> 1);
        const int gxA = x0 + (s & 1) * 16 + g;        // pixel g
        const size_t pixA = (((size_t)b * Hn + gy) * Wn) + gxA;
        const size_t pixB = pixA + 8;                 // pixel g+8

        float2 uwA = *(const float2*)(g_uw + pixA * 8 + 2 * tq);
        float2 uwB = *(const float2*)(g_uw + pixB * 8 + 2 * tq);

        float l0 = bx - uwA.x - acc[s][0];            // px g,   ch 2tq
        float l1 = by - uwA.y - acc[s][1];            // px g,   ch 2tq+1
        float l2 = bx - uwB.x - acc[s][2];            // px g+8, ch 2tq
        float l3 = by - uwB.y - acc[s][3];            // px g+8, ch 2tq+1

        if (last) {
            *(float2*)(out + pixA * 8 + 2 * tq) = make_float2(l0, l1);
            *(float2*)(out + pixB * 8 + 2 * tq) = make_float2(l2, l3);
        } else {
            // softmax over 8 channels = quad (4 lanes, same g) reduction
            float mA = fmaxf(l0, l1);
            mA = fmaxf(mA, __shfl_xor_sync(0xFFFFFFFFu, mA, 1));
            mA = fmaxf(mA, __shfl_xor_sync(0xFFFFFFFFu, mA, 2));
            float e0 = __expf(l0 - mA), e1 = __expf(l1 - mA);
            float sA = e0 + e1;
            sA += __shfl_xor_sync(0xFFFFFFFFu, sA, 1);
            sA += __shfl_xor_sync(0xFFFFFFFFu, sA, 2);
            float invA = __fdividef(1.f, sA);

            float mB = fmaxf(l2, l3);
            mB = fmaxf(mB, __shfl_xor_sync(0xFFFFFFFFu, mB, 1));
            mB = fmaxf(mB, __shfl_xor_sync(0xFFFFFFFFu, mB, 2));
            float e2 = __expf(l2 - mB), e3 = __expf(l3 - mB);
            float sBs = e2 + e3;
            sBs += __shfl_xor_sync(0xFFFFFFFFu, sBs, 1);
            sBs += __shfl_xor_sync(0xFFFFFFFFu, sBs, 2);
            float invB = __fdividef(1.f, sBs);

            qout[pixA * 4 + tq] = pack_bf16(e0 * invA, e1 * invA);
            qout[pixB * 4 + tq] = pack_bf16(e2 * invB, e3 * invB);
        }
    }
}

// ---------------------------------------------------------------------------
extern "C" void kernel_launch(void* const* d_in, const int* in_sizes, int n_in,
                              void* d_out, int out_size) {
    const float* x    = (const float*)d_in[0];
    const float* kint = (const float*)d_in[1];
    const float* ksw  = (const float*)d_in[2];
    const float* ksb  = (const float*)d_in[3];
    float* out = (float*)d_out;

    mrf_prologue<<<(NPIX + 255) / 256, 256>>>(x, ksw);

    dim3 grid(Wn / TX, Hn / TY, Bn);   // 12 x 24 x 32
    for (int it = 0; it < ITERS; it++) {
        mrf_iter_mma<<<grid, 256>>>(kint, ksw, ksb, out,
                                    it & 1, (it == ITERS - 1) ? 1 : 0);
    }
}

// round 15
// speedup vs baseline: 1.3551x; 1.3551x over previous
#include <cuda_runtime.h>
#include <cstdint>

// ---------------- problem constants ----------------
#define Bn    32
#define Hn    384
#define Wn    384
#define ITERS 5
#define NPIX  (Bn * Hn * Wn)
#define NELEM (NPIX * 8)

// ---------------- tile config ----------------
#define TY 16                 // output rows per CTA
#define TX 32                 // output pixels per CTA
#define QR 22                 // q tile rows  (TY + 6 halo)
#define QP 40                 // q tile pixels (TX + 6 halo, padded to 40)

// ---------------- device scratch ----------------
// q marginals stored as bf16x2 words: 4 words per pixel (8 channels)
__device__ uint32_t g_qb[2][NPIX * 4];
__device__ float    g_uw[NELEM];     // u @ W2 (fp32)

__device__ __forceinline__ uint32_t pack_bf16(float lo, float hi) {
    uint32_t r;
    asm("cvt.rn.bf16x2.f32 %0, %1, %2;" : "=r"(r) : "f"(hi), "f"(lo));
    return r;
}

// m16n8k16 bf16 MMA: D(16x8,f32) += A(16x16,row) * B(16x8,col)
__device__ __forceinline__ void mma_bf16(float* c,
                                         uint32_t a0, uint32_t a1,
                                         uint32_t a2, uint32_t a3,
                                         uint32_t b0, uint32_t b1) {
    asm volatile(
        "mma.sync.aligned.m16n8k16.row.col.f32.bf16.bf16.f32 "
        "{%0,%1,%2,%3}, {%4,%5,%6,%7}, {%8,%9}, {%0,%1,%2,%3};"
        : "+f"(c[0]), "+f"(c[1]), "+f"(c[2]), "+f"(c[3])
        : "r"(a0), "r"(a1), "r"(a2), "r"(a3), "r"(b0), "r"(b1));
}

// ---------------------------------------------------------------------------
// Prologue: q0 = softmax(x) (stored bf16x2); uw = (-log(clip(q0))) @ W2 (fp32)
// ---------------------------------------------------------------------------
__global__ void __launch_bounds__(256) mrf_prologue(const float* __restrict__ x,
                                                    const float* __restrict__ ksw) {
    __shared__ float sW[64];
    if (threadIdx.x < 64) sW[threadIdx.x] = ksw[threadIdx.x];
    __syncthreads();

    int p = blockIdx.x * 256 + threadIdx.x;
    if (p >= NPIX) return;
    const float4* xp = (const float4*)(x + (size_t)p * 8);
    float4 a = xp[0], b = xp[1];
    float v[8] = {a.x, a.y, a.z, a.w, b.x, b.y, b.z, b.w};

    float m = v[0];
#pragma unroll
    for (int i = 1; i < 8; i++) m = fmaxf(m, v[i]);
    float e[8], s = 0.f;
#pragma unroll
    for (int i = 0; i < 8; i++) { e[i] = __expf(v[i] - m); s += e[i]; }
    float inv = __fdividef(1.f, s);

    float q[8], u[8];
#pragma unroll
    for (int i = 0; i < 8; i++) {
        q[i] = e[i] * inv;
        u[i] = -__logf(fmaxf(q[i], 1e-6f));
    }
    float uw[8];
#pragma unroll
    for (int d = 0; d < 8; d++) {
        float acc = 0.f;
#pragma unroll
        for (int c = 0; c < 8; c++) acc += u[c] * sW[c * 8 + d];
        uw[d] = acc;
    }
    uint4 qw;
    qw.x = pack_bf16(q[0], q[1]);
    qw.y = pack_bf16(q[2], q[3]);
    qw.z = pack_bf16(q[4], q[5]);
    qw.w = pack_bf16(q[6], q[7]);
    ((uint4*)(&g_qb[0][(size_t)p * 4]))[0] = qw;
    float4* up = (float4*)(&g_uw[(size_t)p * 8]);
    up[0] = make_float4(uw[0], uw[1], uw[2], uw[3]);
    up[1] = make_float4(uw[4], uw[5], uw[6], uw[7]);
}

// ---------------------------------------------------------------------------
// One iteration via bf16 m16n8k16 mma.sync, dx tap-pairs fused into K.
// CTA = 16 rows x 32 px, 8 warps; warp w owns rows {2w,2w+1} x two halves.
// Loop order pi (dx-pair) OUTER, dy INNER: the A-fragment for output row
// rw0+1 at tap dy equals the fragment for output row rw0 at tap dy+1, so
// row-1 fragments slide into the row-0 slot each dy step (register reuse),
// cutting main-loop A LDS from 448 to 256 per warp.
// ---------------------------------------------------------------------------
__global__ void __launch_bounds__(256, 2) mrf_iter_mma(
    const float* __restrict__ kint,
    const float* __restrict__ ksw,
    const float* __restrict__ ksb,
    float* __restrict__ out,
    int parity, int last)
{
    // q tile: bf16x2 words, 4 per pixel (row-major, QP pixels per row)
    __shared__ __align__(16) uint32_t sq[QR * QP * 4];
    // fused tap-pair weights, b0/b1 adjacent for LDS.64:
    // sBp[pair*64 + (tq*8+g)*2 + h], h=0: tap dx0 word, h=1: tap dx0+1 word
    __shared__ __align__(16) uint32_t sBp[28 * 64];

    const int t    = threadIdx.x;
    const int w    = t >> 5;
    const int lane = t & 31;
    const int g    = lane >> 2;    // groupID 0..7
    const int tq   = lane & 3;     // threadID_in_group 0..3

    const int b  = blockIdx.z;
    const int y0 = blockIdx.y * TY;
    const int x0 = blockIdx.x * TX;
    const uint32_t* __restrict__ qin  = g_qb[parity];
    uint32_t* __restrict__       qout = g_qb[parity ^ 1];

    // --- build fused pair weights.
    // index i: pair=i>>6, rem=i&63; h=rem&1; idx=rem>>1; tqi=idx>>3; n=idx&7
    // dx = 2*(pair&3)+h, dy = pair>>2; zero word if dx>6.
    // word = {lo: Bf[tap][2tqi][n], hi: Bf[tap][2tqi+1][n]},
    // Bf[tap][k][n] = sum_{c!=k} K[tap][k][c] * W2[c][n]
    for (int i = t; i < 28 * 64; i += 256) {
        int pair = i >> 6, rem = i & 63;
        int h = rem & 1, idx = rem >> 1, tqi = idx >> 3, n = idx & 7;
        int dy = pair >> 2, dx = 2 * (pair & 3) + h;
        uint32_t word = 0;
        if (dx < 7) {
            int tap = dy * 7 + dx;
            float v0 = 0.f, v1 = 0.f;
            const float* kp0 = kint + tap * 64 + (2 * tqi) * 8;
#pragma unroll
            for (int c = 0; c < 8; c++) {
                float wcn = __ldg(ksw + c * 8 + n);
                if (c != 2 * tqi)     v0 += __ldg(kp0 + c) * wcn;
                if (c != 2 * tqi + 1) v1 += __ldg(kp0 + 8 + c) * wcn;
            }
            word = pack_bf16(v0, v1);
        }
        sBp[i] = word;
    }

    // --- stage q tile (rows y0-3..y0+18, px x0-3..x0+36), bf16x2 words
    for (int i = t; i < QR * QP; i += 256) {
        int qr = i / QP, px = i - qr * QP;
        int gy = y0 + qr - 3, gx = x0 + px - 3;
        uint4 qw = make_uint4(0u, 0u, 0u, 0u);
        if (gy >= 0 && gy < Hn && gx >= 0 && gx < Wn)
            qw = ((const uint4*)(qin + ((((size_t)b * Hn + gy) * Wn) + gx) * 4))[0];
        ((uint4*)sq)[i] = qw;
    }
    __syncthreads();

    // --- mainloop: 4 dx-pairs (outer) x 7 dy (inner, fragment-sliding)
    float acc[4][4];
#pragma unroll
    for (int s = 0; s < 4; s++)
#pragma unroll
        for (int j = 0; j < 4; j++) acc[s][j] = 0.f;

    const int rw0 = 2 * w;

#pragma unroll
    for (int pi = 0; pi < 4; pi++) {
        // fr[rp][h][j]: rp=0 -> image row rw0+dy, rp=1 -> rw0+dy+1;
        // h = x-half (0: px 0-17, 1: px 16-33); j = MMA A regs
        uint32_t fr[2][2][4];
        // initial load: image rows rw0+0 and rw0+1
#pragma unroll
        for (int rp = 0; rp < 2; rp++)
#pragma unroll
            for (int h = 0; h < 2; h++) {
                const int idx = (rw0 + rp) * QP + h * 16 + 2 * pi + g;
                fr[rp][h][0] = sq[idx * 4 + tq];
                fr[rp][h][1] = sq[(idx + 8) * 4 + tq];
                fr[rp][h][2] = sq[(idx + 1) * 4 + tq];
                fr[rp][h][3] = sq[(idx + 9) * 4 + tq];
            }
#pragma unroll
        for (int dy = 0; dy < 7; dy++) {
            uint2 bw = *(const uint2*)(sBp + ((dy * 4 + pi) << 6)
                                           + ((tq * 8 + g) << 1));
            mma_bf16(acc[0], fr[0][0][0], fr[0][0][1], fr[0][0][2], fr[0][0][3],
                     bw.x, bw.y);
            mma_bf16(acc[1], fr[0][1][0], fr[0][1][1], fr[0][1][2], fr[0][1][3],
                     bw.x, bw.y);
            mma_bf16(acc[2], fr[1][0][0], fr[1][0][1], fr[1][0][2], fr[1][0][3],
                     bw.x, bw.y);
            mma_bf16(acc[3], fr[1][1][0], fr[1][1][1], fr[1][1][2], fr[1][1][3],
                     bw.x, bw.y);
            if (dy < 6) {
                // slide: row-1 fragments become row-0; load new row-1
#pragma unroll
                for (int h = 0; h < 2; h++) {
#pragma unroll
                    for (int j = 0; j < 4; j++) fr[0][h][j] = fr[1][h][j];
                    const int idx = (rw0 + dy + 2) * QP + h * 16 + 2 * pi + g;
                    fr[1][h][0] = sq[idx * 4 + tq];
                    fr[1][h][1] = sq[(idx + 8) * 4 + tq];
                    fr[1][h][2] = sq[(idx + 1) * 4 + tq];
                    fr[1][h][3] = sq[(idx + 9) * 4 + tq];
                }
            }
        }
    }

    // --- epilogue: lane owns pixels (g, g+8) x channels (2tq, 2tq+1) per strip
    const float bx = __ldg(ksb + 2 * tq);
    const float by = __ldg(ksb + 2 * tq + 1);

#pragma unroll
    for (int s = 0; s < 4; s++) {
        const int gy = y0 + rw0 + (s >> 1);
        const int gxA = x0 + (s & 1) * 16 + g;        // pixel g
        const size_t pixA = (((size_t)b * Hn + gy) * Wn) + gxA;
        const size_t pixB = pixA + 8;                 // pixel g+8
        // acc mapping: acc[0]=(r0,h0), acc[1]=(r0,h1), acc[2]=(r1,h0), acc[3]=(r1,h1)
        const float* ac = acc[(s >> 1) * 2 + (s & 1)];

        float2 uwA = *(const float2*)(g_uw + pixA * 8 + 2 * tq);
        float2 uwB = *(const float2*)(g_uw + pixB * 8 + 2 * tq);

        float l0 = bx - uwA.x - ac[0];                // px g,   ch 2tq
        float l1 = by - uwA.y - ac[1];                // px g,   ch 2tq+1
        float l2 = bx - uwB.x - ac[2];                // px g+8, ch 2tq
        float l3 = by - uwB.y - ac[3];                // px g+8, ch 2tq+1

        if (last) {
            *(float2*)(out + pixA * 8 + 2 * tq) = make_float2(l0, l1);
            *(float2*)(out + pixB * 8 + 2 * tq) = make_float2(l2, l3);
        } else {
            // softmax over 8 channels = quad (4 lanes, same g) reduction
            float mA = fmaxf(l0, l1);
            mA = fmaxf(mA, __shfl_xor_sync(0xFFFFFFFFu, mA, 1));
            mA = fmaxf(mA, __shfl_xor_sync(0xFFFFFFFFu, mA, 2));
            float e0 = __expf(l0 - mA), e1 = __expf(l1 - mA);
            float sA = e0 + e1;
            sA += __shfl_xor_sync(0xFFFFFFFFu, sA, 1);
            sA += __shfl_xor_sync(0xFFFFFFFFu, sA, 2);
            float invA = __fdividef(1.f, sA);

            float mB = fmaxf(l2, l3);
            mB = fmaxf(mB, __shfl_xor_sync(0xFFFFFFFFu, mB, 1));
            mB = fmaxf(mB, __shfl_xor_sync(0xFFFFFFFFu, mB, 2));
            float e2 = __expf(l2 - mB), e3 = __expf(l3 - mB);
            float sBs = e2 + e3;
            sBs += __shfl_xor_sync(0xFFFFFFFFu, sBs, 1);
            sBs += __shfl_xor_sync(0xFFFFFFFFu, sBs, 2);
            float invB = __fdividef(1.f, sBs);

            qout[pixA * 4 + tq] = pack_bf16(e0 * invA, e1 * invA);
            qout[pixB * 4 + tq] = pack_bf16(e2 * invB, e3 * invB);
        }
    }
}

// ---------------------------------------------------------------------------
extern "C" void kernel_launch(void* const* d_in, const int* in_sizes, int n_in,
                              void* d_out, int out_size) {
    const float* x    = (const float*)d_in[0];
    const float* kint = (const float*)d_in[1];
    const float* ksw  = (const float*)d_in[2];
    const float* ksb  = (const float*)d_in[3];
    float* out = (float*)d_out;

    mrf_prologue<<<(NPIX + 255) / 256, 256>>>(x, ksw);

    dim3 grid(Wn / TX, Hn / TY, Bn);   // 12 x 24 x 32
    for (int it = 0; it < ITERS; it++) {
        mrf_iter_mma<<<grid, 256>>>(kint, ksw, ksb, out,
                                    it & 1, (it == ITERS - 1) ? 1 : 0);
    }
}